// round 1
// baseline (speedup 1.0000x reference)
#include <cuda_runtime.h>

#define HOPS 512
#define WINW 1024
#define NHARM 100
#define TT 400
#define BB 4

// Accurate-enough fast cosine: Cody-Waite 2-term range reduction + MUFU.COS.
// |x| <= ~90 rad here; reduced residual error ~1e-7 rad, MUFU abs err ~1.3e-6.
__device__ __forceinline__ float cos_r(float x) {
    float q = rintf(x * 0.15915494309189535f);   // x / (2*pi)
    x = fmaf(q, -6.28125f, x);                   // hi part (exact in fp32)
    x = fmaf(q, -1.9353071795864769e-3f, x);     // lo part
    return __cosf(x);
}

__global__ void zero_out_kernel(float* __restrict__ out, int n) {
    int i = blockIdx.x * blockDim.x + threadIdx.x;
    if (i < n) out[i] = 0.0f;
}

// One warp per frame (b,t). 4 warps per block so all 4 SMSPs get work.
// Lane l owns window positions w = l + 32*k, k = 0..31.
// Per harmonic: seed c1 = a*cos(theta(w=l)), c0 = a*cos(theta(w=l-32)),
// r = 2*cos(32*delta); then Chebyshev recurrence with the amplitude folded
// into the seeds (linear recurrence), so the inner loop is FADD + FFMA only.
__global__ __launch_bounds__(128) void sinstack_kernel(
    const float* __restrict__ ampl,
    const float* __restrict__ phase,
    const float* __restrict__ f0,
    float* __restrict__ out)
{
    __shared__ float sh_d[4][NHARM];   // delta = 2*pi*f0/SR
    __shared__ float sh_p[4][NHARM];   // phase
    __shared__ float sh_a[4][NHARM];   // ampl

    const int warp = threadIdx.x >> 5;
    const int lane = threadIdx.x & 31;
    const int fid  = blockIdx.x * 4 + warp;    // 0..1599
    const int b = fid / TT;
    const int t = fid - b * TT;

    // Preload this frame's per-harmonic params into shared memory.
    const float K2PI_SR = 6.283185307179586f / 44100.0f;
    const int base = b * NHARM * TT + t;
    for (int n = lane; n < NHARM; n += 32) {
        int idx = base + n * TT;
        sh_d[warp][n] = f0[idx] * K2PI_SR;
        sh_p[warp][n] = phase[idx];
        sh_a[warp][n] = ampl[idx];
    }
    __syncwarp();

    float acc[32];
    #pragma unroll
    for (int k = 0; k < 32; k++) acc[k] = 0.0f;

    const float wpos = (float)(lane - HOPS);   // x offset at k=0

    for (int n = 0; n < NHARM; n++) {
        float dlt = sh_d[warp][n];
        float ph  = sh_p[warp][n];
        float a   = sh_a[warp][n];

        float d  = 32.0f * dlt;                 // stride angle (<= ~4.8 rad)
        float th = fmaf(wpos, dlt, ph);         // theta at w = lane
        float c1 = a * cos_r(th);               // term at k=0 (amp folded in)
        float c0 = a * cos_r(th - d);           // term at k=-1
        float r  = 2.0f * cos_r(d);

        #pragma unroll
        for (int k = 0; k < 32; k++) {
            acc[k] += c1;
            float c2 = fmaf(r, c1, -c0);        // neg folds into FFMA
            c0 = c1;
            c1 = c2;
        }
    }

    // Hann window + overlap-add. Frame t covers output [(t-1)*512, (t+1)*512).
    float* outb = out + b * (TT * HOPS);
    const int pbase = (t - 1) * HOPS + lane;
    const float HSTEP = 6.283185307179586f / 1024.0f;
    #pragma unroll
    for (int k = 0; k < 32; k++) {
        int w = lane + 32 * k;
        float hann = fmaf(-0.5f, __cosf((float)w * HSTEP), 0.5f);
        int p = pbase + 32 * k;
        if (p >= 0 && p < TT * HOPS) {
            atomicAdd(outb + p, acc[k] * hann);
        }
    }
}

extern "C" void kernel_launch(void* const* d_in, const int* in_sizes, int n_in,
                              void* d_out, int out_size) {
    const float* ampl  = (const float*)d_in[0];
    const float* phase = (const float*)d_in[1];
    const float* f0    = (const float*)d_in[2];
    float* out = (float*)d_out;

    zero_out_kernel<<<(out_size + 255) / 256, 256>>>(out, out_size);
    sinstack_kernel<<<400, 128>>>(ampl, phase, f0, out);
}

// round 2
// speedup vs baseline: 1.2152x; 1.2152x over previous
#include <cuda_runtime.h>

#define HOPS 512
#define NHARM 100
#define TT 400
#define NHALF 50   // harmonics per warp

typedef unsigned long long ull;

// ---- packed f32x2 helpers (sm_103a) ----
__device__ __forceinline__ ull pack2(float lo, float hi) {
    ull r; asm("mov.b64 %0, {%1, %2};" : "=l"(r) : "f"(lo), "f"(hi)); return r;
}
__device__ __forceinline__ void unpack2(ull v, float& lo, float& hi) {
    asm("mov.b64 {%0, %1}, %2;" : "=f"(lo), "=f"(hi) : "l"(v));
}
__device__ __forceinline__ ull fma2(ull a, ull b, ull c) {
    ull d; asm("fma.rn.f32x2 %0, %1, %2, %3;" : "=l"(d) : "l"(a), "l"(b), "l"(c)); return d;
}
__device__ __forceinline__ ull add2(ull a, ull b) {
    ull d; asm("add.rn.f32x2 %0, %1, %2;" : "=l"(d) : "l"(a), "l"(b)); return d;
}

// Cody-Waite 2-term range reduction + MUFU.COS (|x| <= ~90 rad here).
__device__ __forceinline__ float cos_r(float x) {
    float q = rintf(x * 0.15915494309189535f);
    x = fmaf(q, -6.28125f, x);
    x = fmaf(q, -1.9353071795864769e-3f, x);
    return __cosf(x);
}

__global__ void zero_out_kernel(float* __restrict__ out, int n) {
    int i = blockIdx.x * blockDim.x + threadIdx.x;
    if (i < n) out[i] = 0.0f;
}

// One warp per (frame, harmonic-half). Lane l owns w = l + 32k, k=0..31.
// Two harmonics packed per f32x2 register; Chebyshev recurrence with
// alternating-sign multiplier (sign pattern sigma = ++--) so no subtraction
// or operand negation is ever needed in the inner loop:
//   p_{k+1} = fma2(R_k, p_k, p_{k-1}),  R_k = +r (odd k+1) / -r (even k+1)
//   acc[k] += p_k   (sigma folded out in the epilogue, free in the FMUL)
__global__ __launch_bounds__(128) void sinstack_kernel(
    const float* __restrict__ ampl,
    const float* __restrict__ phase,
    const float* __restrict__ f0,
    float* __restrict__ out)
{
    __shared__ float sh_d[4][NHALF];
    __shared__ float sh_p[4][NHALF];
    __shared__ float sh_a[4][NHALF];

    const int warp = threadIdx.x >> 5;
    const int lane = threadIdx.x & 31;
    const int gw   = blockIdx.x * 4 + warp;      // 0..3199
    const int frame = gw >> 1;                   // 0..1599
    const int half  = gw & 1;                    // harmonic half
    const int b = frame / TT;
    const int t = frame - b * TT;

    // Preload this warp's 50 harmonics' params.
    const float K2PI_SR = 6.283185307179586f / 44100.0f;
    const int base = b * NHARM * TT + (half * NHALF) * TT + t;
    for (int j = lane; j < NHALF; j += 32) {
        int idx = base + j * TT;
        sh_d[warp][j] = f0[idx] * K2PI_SR;
        sh_p[warp][j] = phase[idx];
        sh_a[warp][j] = ampl[idx];
    }
    __syncwarp();

    ull acc[32];
    #pragma unroll
    for (int k = 0; k < 32; k++) acc[k] = 0ull;

    const float wpos = (float)(lane - HOPS);

    for (int j = 0; j < NHALF; j += 2) {
        // --- scalar seeds for harmonic pair (A = j, B = j+1) ---
        float dA = sh_d[warp][j],     pA = sh_p[warp][j],     aA = sh_a[warp][j];
        float dB = sh_d[warp][j + 1], pB = sh_p[warp][j + 1], aB = sh_a[warp][j + 1];

        float DA = 32.0f * dA,  DB = 32.0f * dB;        // stride angles
        float thA = fmaf(wpos, dA, pA), thB = fmaf(wpos, dB, pB);

        float c0A  =  aA * cos_r(thA);                  // c_0
        float cm1A = -aA * cos_r(thA - DA);             // p_{-1} = -c_{-1}
        float rA   = 2.0f * cos_r(DA);
        float c0B  =  aB * cos_r(thB);
        float cm1B = -aB * cos_r(thB - DB);
        float rB   = 2.0f * cos_r(DB);

        ull p_prev = pack2(cm1A, cm1B);   // p_{-1}
        ull p_cur  = pack2(c0A,  c0B);    // p_0
        ull rp = pack2(rA, rB);
        ull rn = pack2(-rA, -rB);

        #pragma unroll
        for (int k = 0; k < 32; k++) {
            acc[k] = add2(acc[k], p_cur);               // accumulates sigma_k * c_k
            ull nxt = fma2(((k + 1) & 1) ? rp : rn, p_cur, p_prev);
            p_prev = p_cur;
            p_cur = nxt;
        }
    }

    // Hann window + overlap-add. Frame t covers output [(t-1)*512, (t+1)*512).
    float* outb = out + b * (TT * HOPS);
    const int pbase = (t - 1) * HOPS + lane;
    const float HSTEP = 6.283185307179586f / 1024.0f;
    #pragma unroll
    for (int k = 0; k < 32; k++) {
        float lo, hi;
        unpack2(acc[k], lo, hi);
        float s = lo + hi;
        // sigma_k = + for k%4 in {0,1}, - for {2,3}: fold into the window mul
        int w = lane + 32 * k;
        float hann = fmaf(-0.5f, __cosf((float)w * HSTEP), 0.5f);
        float v = (((k >> 1) & 1) == 0) ? (s * hann) : (s * (-hann));
        int p = pbase + 32 * k;
        if (p >= 0 && p < TT * HOPS) {
            atomicAdd(outb + p, v);
        }
    }
}

extern "C" void kernel_launch(void* const* d_in, const int* in_sizes, int n_in,
                              void* d_out, int out_size) {
    const float* ampl  = (const float*)d_in[0];
    const float* phase = (const float*)d_in[1];
    const float* f0    = (const float*)d_in[2];
    float* out = (float*)d_out;

    zero_out_kernel<<<(out_size + 255) / 256, 256>>>(out, out_size);
    sinstack_kernel<<<800, 128>>>(ampl, phase, f0, out);
}

// round 3
// speedup vs baseline: 1.2579x; 1.0351x over previous
#include <cuda_runtime.h>

#define HOPS 512
#define NHARM 100
#define TT 400
#define NHALF 50
#define NPAIR 25

typedef unsigned long long ull;

// ---- packed f32x2 helpers (sm_103a) ----
__device__ __forceinline__ ull pack2(float lo, float hi) {
    ull r; asm("mov.b64 %0, {%1, %2};" : "=l"(r) : "f"(lo), "f"(hi)); return r;
}
__device__ __forceinline__ void unpack2(ull v, float& lo, float& hi) {
    asm("mov.b64 {%0, %1}, %2;" : "=f"(lo), "=f"(hi) : "l"(v));
}
__device__ __forceinline__ ull fma2(ull a, ull b, ull c) {
    ull d; asm("fma.rn.f32x2 %0, %1, %2, %3;" : "=l"(d) : "l"(a), "l"(b), "l"(c)); return d;
}
__device__ __forceinline__ ull add2(ull a, ull b) {
    ull d; asm("add.rn.f32x2 %0, %1, %2;" : "=l"(d) : "l"(a), "l"(b)); return d;
}
__device__ __forceinline__ ull mul2(ull a, ull b) {
    ull d; asm("mul.rn.f32x2 %0, %1, %2;" : "=l"(d) : "l"(a), "l"(b)); return d;
}

// One warp per (frame, harmonic-half). Lane l owns w = l + 32k, k=0..31.
// Chebyshev recurrence with alternating-sign multiplier (sigma = ++--),
// 2 harmonics per f32x2 register: 1 fma2 + 1 add2 per 2 harmonic-terms.
// Seeds are computed packed: one Cody-Waite reduction (magic-number rint in
// f32x2), then cos(th-D) via the angle-difference identity so only th needs
// reduction; D (<= 4.75 rad) uses raw MUFU.
__global__ __launch_bounds__(128, 6) void sinstack_kernel(
    const float* __restrict__ ampl,
    const float* __restrict__ phase,
    const float* __restrict__ f0,
    float* __restrict__ out)
{
    __shared__ ull sh_d2[4][NPAIR];    // delta pairs
    __shared__ ull sh_p2[4][NPAIR];    // phase pairs
    __shared__ ull sh_a2[4][NPAIR];    // +ampl pairs
    __shared__ ull sh_an2[4][NPAIR];   // -ampl pairs
    __shared__ float sh_hann[1024];

    const int warp = threadIdx.x >> 5;
    const int lane = threadIdx.x & 31;
    const int gw   = blockIdx.x * 4 + warp;
    const int frame = gw >> 1;
    const int half  = gw & 1;
    const int b = frame / TT;
    const int t = frame - b * TT;

    // Hann window table (block-shared, sign applied at use).
    {
        const float HSTEP = 6.283185307179586f / 1024.0f;
        #pragma unroll
        for (int i = 0; i < 8; i++) {
            int w = threadIdx.x + 128 * i;
            sh_hann[w] = fmaf(-0.5f, __cosf((float)w * HSTEP), 0.5f);
        }
    }

    // Preload this warp's 50 harmonics' params (packed pair layout).
    {
        const float K2PI_SR = 6.283185307179586f / 44100.0f;
        const int base = b * NHARM * TT + (half * NHALF) * TT + t;
        float* fd = (float*)&sh_d2[warp][0];
        float* fp = (float*)&sh_p2[warp][0];
        float* fa = (float*)&sh_a2[warp][0];
        float* fn = (float*)&sh_an2[warp][0];
        for (int j = lane; j < NHALF; j += 32) {
            int idx = base + j * TT;
            float a = ampl[idx];
            fd[j] = f0[idx] * K2PI_SR;
            fp[j] = phase[idx];
            fa[j] = a;
            fn[j] = -a;
        }
    }
    __syncthreads();

    ull acc[32];
    #pragma unroll
    for (int k = 0; k < 32; k++) acc[k] = 0ull;

    const float wpos = (float)(lane - HOPS);
    const ull wpos2   = pack2(wpos, wpos);
    const ull K32     = pack2(32.0f, 32.0f);
    const ull INV2PI2 = pack2(0.15915494309189535f, 0.15915494309189535f);
    const ull MAGIC2  = pack2(12582912.0f, 12582912.0f);
    const ull MAGICN2 = pack2(-12582912.0f, -12582912.0f);
    const ull C1N2    = pack2(-6.28125f, -6.28125f);
    const ull C2N2    = pack2(-1.9353071795864769e-3f, -1.9353071795864769e-3f);
    const ull NEGTWO2 = pack2(-2.0f, -2.0f);

    for (int jp = 0; jp < NPAIR; jp++) {
        ull dd  = sh_d2[warp][jp];
        ull pp  = sh_p2[warp][jp];
        ull aa  = sh_a2[warp][jp];
        ull aan = sh_an2[warp][jp];

        // theta at w = lane, packed Cody-Waite reduction
        ull D2 = mul2(dd, K32);                 // stride angle (<= 4.75 rad)
        ull x2 = fma2(wpos2, dd, pp);
        ull y2 = mul2(x2, INV2PI2);
        ull q2 = add2(add2(y2, MAGIC2), MAGICN2);   // rint via magic const
        x2 = fma2(q2, C1N2, x2);
        x2 = fma2(q2, C2N2, x2);

        float xA, xB, DA, DB;
        unpack2(x2, xA, xB);
        unpack2(D2, DA, DB);
        float cthA = __cosf(xA), sthA = __sinf(xA);
        float cthB = __cosf(xB), sthB = __sinf(xB);
        float cDA  = __cosf(DA), sDA  = __sinf(DA);
        float cDB  = __cosf(DB), sDB  = __sinf(DB);
        ull cth2 = pack2(cthA, cthB);
        ull sth2 = pack2(sthA, sthB);
        ull cD2  = pack2(cDA, cDB);
        ull sD2  = pack2(sDA, sDB);

        ull p_cur  = mul2(aa, cth2);            // +a*cos(th) = p_0
        ull u2     = mul2(aan, sth2);           // -a*sin(th)
        ull v2     = mul2(u2, sD2);
        ull c0n2   = mul2(aan, cth2);
        ull p_prev = fma2(c0n2, cD2, v2);       // -a*cos(th-D) = p_{-1}
        ull rp = add2(cD2, cD2);                // +2cos(D)
        ull rn = mul2(cD2, NEGTWO2);            // -2cos(D)

        #pragma unroll
        for (int k = 0; k < 32; k++) {
            acc[k] = add2(acc[k], p_cur);       // accumulates sigma_k * c_k
            ull nxt = fma2(((k + 1) & 1) ? rp : rn, p_cur, p_prev);
            p_prev = p_cur;
            p_cur = nxt;
        }
    }

    // Hann window + overlap-add. Frame t covers output [(t-1)*512, (t+1)*512).
    float* outb = out + b * (TT * HOPS);
    const int pbase = (t - 1) * HOPS + lane;
    #pragma unroll
    for (int k = 0; k < 32; k++) {
        float lo, hi;
        unpack2(acc[k], lo, hi);
        float s = lo + hi;
        float hann = sh_hann[lane + 32 * k];
        // sigma_k = + for k%4 in {0,1}, - for {2,3}: fold into window mul
        float v = (((k >> 1) & 1) == 0) ? (s * hann) : (s * (-hann));
        int p = pbase + 32 * k;
        if (p >= 0 && p < TT * HOPS) {
            atomicAdd(outb + p, v);
        }
    }
}

extern "C" void kernel_launch(void* const* d_in, const int* in_sizes, int n_in,
                              void* d_out, int out_size) {
    const float* ampl  = (const float*)d_in[0];
    const float* phase = (const float*)d_in[1];
    const float* f0    = (const float*)d_in[2];
    float* out = (float*)d_out;

    cudaMemsetAsync(out, 0, (size_t)out_size * sizeof(float));
    sinstack_kernel<<<800, 128>>>(ampl, phase, f0, out);
}

// round 4
// speedup vs baseline: 1.3119x; 1.0429x over previous
#include <cuda_runtime.h>

#define HOPS 512
#define NHARM 100
#define TT 400
#define NHALF 50
#define NPAIR 25

typedef unsigned long long ull;

// ---- packed f32x2 helpers (sm_103a) ----
__device__ __forceinline__ ull pack2(float lo, float hi) {
    ull r; asm("mov.b64 %0, {%1, %2};" : "=l"(r) : "f"(lo), "f"(hi)); return r;
}
__device__ __forceinline__ void unpack2(ull v, float& lo, float& hi) {
    asm("mov.b64 {%0, %1}, %2;" : "=f"(lo), "=f"(hi) : "l"(v));
}
__device__ __forceinline__ ull fma2(ull a, ull b, ull c) {
    ull d; asm("fma.rn.f32x2 %0, %1, %2, %3;" : "=l"(d) : "l"(a), "l"(b), "l"(c)); return d;
}
__device__ __forceinline__ ull add2(ull a, ull b) {
    ull d; asm("add.rn.f32x2 %0, %1, %2;" : "=l"(d) : "l"(a), "l"(b)); return d;
}
__device__ __forceinline__ ull mul2(ull a, ull b) {
    ull d; asm("mul.rn.f32x2 %0, %1, %2;" : "=l"(d) : "l"(a), "l"(b)); return d;
}

struct Chain { ull p_prev, p_cur, rp, rn; };

// Seeds for one packed harmonic pair: Cody-Waite reduce theta (packed),
// cos(th-D) via angle-difference identity (D <= 4.75 rad, raw MUFU).
__device__ __forceinline__ Chain seed_pair(ull dd, ull pp, ull aa, ull aan, ull wpos2) {
    const ull K32     = pack2(32.0f, 32.0f);
    const ull INV2PI2 = pack2(0.15915494309189535f, 0.15915494309189535f);
    const ull MAGIC2  = pack2(12582912.0f, 12582912.0f);
    const ull MAGICN2 = pack2(-12582912.0f, -12582912.0f);
    const ull C1N2    = pack2(-6.28125f, -6.28125f);
    const ull C2N2    = pack2(-1.9353071795864769e-3f, -1.9353071795864769e-3f);
    const ull NEGTWO2 = pack2(-2.0f, -2.0f);

    ull D2 = mul2(dd, K32);
    ull x2 = fma2(wpos2, dd, pp);
    ull y2 = mul2(x2, INV2PI2);
    ull q2 = add2(add2(y2, MAGIC2), MAGICN2);
    x2 = fma2(q2, C1N2, x2);
    x2 = fma2(q2, C2N2, x2);

    float xA, xB, DA, DB;
    unpack2(x2, xA, xB);
    unpack2(D2, DA, DB);
    ull cth2 = pack2(__cosf(xA), __cosf(xB));
    ull sth2 = pack2(__sinf(xA), __sinf(xB));
    ull cD2  = pack2(__cosf(DA), __cosf(DB));
    ull sD2  = pack2(__sinf(DA), __sinf(DB));

    Chain c;
    c.p_cur  = mul2(aa, cth2);                 // +a*cos(th)
    ull u2   = mul2(mul2(aan, sth2), sD2);     // -a*sin(th)*sin(D)
    c.p_prev = fma2(mul2(aan, cth2), cD2, u2); // -a*cos(th-D)
    c.rp = add2(cD2, cD2);                     // +2cos(D)
    c.rn = mul2(cD2, NEGTWO2);                 // -2cos(D)
    return c;
}

// One warp per (frame, harmonic-half); lane l owns w = l + 32k, k=0..31.
// TWO independent packed Chebyshev chains advanced in lockstep (4 harmonics
// per k-step) so each warp sustains ~1 IPC instead of being chained at 0.5.
// Sigma trick (++--) keeps the recurrence subtraction-free; sign folded into
// the Hann multiply in the epilogue.
__global__ __launch_bounds__(128, 6) void sinstack_kernel(
    const float* __restrict__ ampl,
    const float* __restrict__ phase,
    const float* __restrict__ f0,
    float* __restrict__ out)
{
    __shared__ ull sh_d2[4][NPAIR];
    __shared__ ull sh_p2[4][NPAIR];
    __shared__ ull sh_a2[4][NPAIR];
    __shared__ ull sh_an2[4][NPAIR];
    __shared__ float sh_hann[1024];

    const int warp = threadIdx.x >> 5;
    const int lane = threadIdx.x & 31;
    const int gw   = blockIdx.x * 4 + warp;
    const int frame = gw >> 1;
    const int half  = gw & 1;
    const int b = frame / TT;
    const int t = frame - b * TT;

    {
        const float HSTEP = 6.283185307179586f / 1024.0f;
        #pragma unroll
        for (int i = 0; i < 8; i++) {
            int w = threadIdx.x + 128 * i;
            sh_hann[w] = fmaf(-0.5f, __cosf((float)w * HSTEP), 0.5f);
        }
    }

    {
        const float K2PI_SR = 6.283185307179586f / 44100.0f;
        const int base = b * NHARM * TT + (half * NHALF) * TT + t;
        float* fd = (float*)&sh_d2[warp][0];
        float* fp = (float*)&sh_p2[warp][0];
        float* fa = (float*)&sh_a2[warp][0];
        float* fn = (float*)&sh_an2[warp][0];
        for (int j = lane; j < NHALF; j += 32) {
            int idx = base + j * TT;
            float a = ampl[idx];
            fd[j] = f0[idx] * K2PI_SR;
            fp[j] = phase[idx];
            fa[j] = a;
            fn[j] = -a;
        }
    }
    __syncthreads();

    ull acc[32];
    #pragma unroll
    for (int k = 0; k < 32; k++) acc[k] = 0ull;

    const float wpos = (float)(lane - HOPS);
    const ull wpos2 = pack2(wpos, wpos);

    // 12 dual-chain iterations (pairs 0..23), then one single-chain tail (pair 24).
    for (int q = 0; q < 12; q++) {
        int jA = 2 * q, jB = 2 * q + 1;
        Chain A = seed_pair(sh_d2[warp][jA], sh_p2[warp][jA],
                            sh_a2[warp][jA], sh_an2[warp][jA], wpos2);
        Chain B = seed_pair(sh_d2[warp][jB], sh_p2[warp][jB],
                            sh_a2[warp][jB], sh_an2[warp][jB], wpos2);

        #pragma unroll
        for (int k = 0; k < 32; k++) {
            acc[k] = add2(acc[k], A.p_cur);
            acc[k] = add2(acc[k], B.p_cur);
            ull rA = ((k + 1) & 1) ? A.rp : A.rn;
            ull rB = ((k + 1) & 1) ? B.rp : B.rn;
            ull nA = fma2(rA, A.p_cur, A.p_prev);
            ull nB = fma2(rB, B.p_cur, B.p_prev);
            A.p_prev = A.p_cur; A.p_cur = nA;
            B.p_prev = B.p_cur; B.p_cur = nB;
        }
    }
    {
        Chain A = seed_pair(sh_d2[warp][24], sh_p2[warp][24],
                            sh_a2[warp][24], sh_an2[warp][24], wpos2);
        #pragma unroll
        for (int k = 0; k < 32; k++) {
            acc[k] = add2(acc[k], A.p_cur);
            ull nA = fma2(((k + 1) & 1) ? A.rp : A.rn, A.p_cur, A.p_prev);
            A.p_prev = A.p_cur; A.p_cur = nA;
        }
    }

    // Hann window + overlap-add. Frame t covers output [(t-1)*512, (t+1)*512).
    float* outb = out + b * (TT * HOPS);
    const int pbase = (t - 1) * HOPS + lane;
    #pragma unroll
    for (int k = 0; k < 32; k++) {
        float lo, hi;
        unpack2(acc[k], lo, hi);
        float s = lo + hi;
        float hann = sh_hann[lane + 32 * k];
        float v = (((k >> 1) & 1) == 0) ? (s * hann) : (s * (-hann));
        int p = pbase + 32 * k;
        if (p >= 0 && p < TT * HOPS) {
            atomicAdd(outb + p, v);
        }
    }
}

extern "C" void kernel_launch(void* const* d_in, const int* in_sizes, int n_in,
                              void* d_out, int out_size) {
    const float* ampl  = (const float*)d_in[0];
    const float* phase = (const float*)d_in[1];
    const float* f0    = (const float*)d_in[2];
    float* out = (float*)d_out;

    cudaMemsetAsync(out, 0, (size_t)out_size * sizeof(float));
    sinstack_kernel<<<800, 128>>>(ampl, phase, f0, out);
}

// round 5
// speedup vs baseline: 1.3135x; 1.0013x over previous
#include <cuda_runtime.h>

#define HOPS 512
#define NHARM 100
#define TT 400
#define NHALF 50
#define NPAIR 25
#define KSTEPS 16   // window samples per lane (half window per warp)

typedef unsigned long long ull;

// ---- packed f32x2 helpers (sm_103a) ----
__device__ __forceinline__ ull pack2(float lo, float hi) {
    ull r; asm("mov.b64 %0, {%1, %2};" : "=l"(r) : "f"(lo), "f"(hi)); return r;
}
__device__ __forceinline__ void unpack2(ull v, float& lo, float& hi) {
    asm("mov.b64 {%0, %1}, %2;" : "=f"(lo), "=f"(hi) : "l"(v));
}
__device__ __forceinline__ ull fma2(ull a, ull b, ull c) {
    ull d; asm("fma.rn.f32x2 %0, %1, %2, %3;" : "=l"(d) : "l"(a), "l"(b), "l"(c)); return d;
}
__device__ __forceinline__ ull add2(ull a, ull b) {
    ull d; asm("add.rn.f32x2 %0, %1, %2;" : "=l"(d) : "l"(a), "l"(b)); return d;
}
__device__ __forceinline__ ull mul2(ull a, ull b) {
    ull d; asm("mul.rn.f32x2 %0, %1, %2;" : "=l"(d) : "l"(a), "l"(b)); return d;
}

struct Chain { ull p_prev, p_cur, rp, rn; };

// Seeds for one packed harmonic pair at window offset wpos:
// packed Cody-Waite reduction of theta, cos(th-D) via angle-difference
// identity (stride angle D <= 4.75 rad uses raw MUFU).
__device__ __forceinline__ Chain seed_pair(ull dd, ull pp, ull aa, ull aan, ull wpos2) {
    const ull K32     = pack2(32.0f, 32.0f);
    const ull INV2PI2 = pack2(0.15915494309189535f, 0.15915494309189535f);
    const ull MAGIC2  = pack2(12582912.0f, 12582912.0f);
    const ull MAGICN2 = pack2(-12582912.0f, -12582912.0f);
    const ull C1N2    = pack2(-6.28125f, -6.28125f);
    const ull C2N2    = pack2(-1.9353071795864769e-3f, -1.9353071795864769e-3f);
    const ull NEGTWO2 = pack2(-2.0f, -2.0f);

    ull D2 = mul2(dd, K32);
    ull x2 = fma2(wpos2, dd, pp);
    ull y2 = mul2(x2, INV2PI2);
    ull q2 = add2(add2(y2, MAGIC2), MAGICN2);
    x2 = fma2(q2, C1N2, x2);
    x2 = fma2(q2, C2N2, x2);

    float xA, xB, DA, DB;
    unpack2(x2, xA, xB);
    unpack2(D2, DA, DB);
    ull cth2 = pack2(__cosf(xA), __cosf(xB));
    ull sth2 = pack2(__sinf(xA), __sinf(xB));
    ull cD2  = pack2(__cosf(DA), __cosf(DB));
    ull sD2  = pack2(__sinf(DA), __sinf(DB));

    Chain c;
    c.p_cur  = mul2(aa, cth2);                 // +a*cos(th)
    ull u2   = mul2(mul2(aan, sth2), sD2);     // -a*sin(th)*sin(D)
    c.p_prev = fma2(mul2(aan, cth2), cD2, u2); // -a*cos(th-D)
    c.rp = add2(cD2, cD2);                     // +2cos(D)
    c.rn = mul2(cD2, NEGTWO2);                 // -2cos(D)
    return c;
}

// One warp per (frame, harmonic-half, window-half). Lane l owns
// w = wh*512 + l + 32k, k = 0..15. Only 16 packed accumulators live
// (32 regs) -> no register spills. Two independent packed Chebyshev chains
// per iteration; sigma trick (++--) keeps the loop subtraction-free, sign
// folded into the Hann multiply.
__global__ __launch_bounds__(128, 6) void sinstack_kernel(
    const float* __restrict__ ampl,
    const float* __restrict__ phase,
    const float* __restrict__ f0,
    float* __restrict__ out)
{
    __shared__ ull sh_d2[4][NPAIR];
    __shared__ ull sh_p2[4][NPAIR];
    __shared__ ull sh_a2[4][NPAIR];
    __shared__ ull sh_an2[4][NPAIR];
    __shared__ float sh_hann[1024];

    const int warp = threadIdx.x >> 5;
    const int lane = threadIdx.x & 31;
    const int gw   = blockIdx.x * 4 + warp;     // 0..6399
    const int frame = gw >> 2;                  // 0..1599
    const int half  = (gw >> 1) & 1;            // harmonic half
    const int wh    = gw & 1;                   // window half
    const int b = frame / TT;
    const int t = frame - b * TT;

    {
        const float HSTEP = 6.283185307179586f / 1024.0f;
        #pragma unroll
        for (int i = 0; i < 8; i++) {
            int w = threadIdx.x + 128 * i;
            sh_hann[w] = fmaf(-0.5f, __cosf((float)w * HSTEP), 0.5f);
        }
    }

    {
        const float K2PI_SR = 6.283185307179586f / 44100.0f;
        const int base = b * NHARM * TT + (half * NHALF) * TT + t;
        float* fd = (float*)&sh_d2[warp][0];
        float* fp = (float*)&sh_p2[warp][0];
        float* fa = (float*)&sh_a2[warp][0];
        float* fn = (float*)&sh_an2[warp][0];
        for (int j = lane; j < NHALF; j += 32) {
            int idx = base + j * TT;
            float a = ampl[idx];
            fd[j] = f0[idx] * K2PI_SR;
            fp[j] = phase[idx];
            fa[j] = a;
            fn[j] = -a;
        }
    }
    __syncthreads();

    ull acc[KSTEPS];
    #pragma unroll
    for (int k = 0; k < KSTEPS; k++) acc[k] = 0ull;

    const float wpos = (float)(wh * 512 + lane - HOPS);
    const ull wpos2 = pack2(wpos, wpos);

    // 12 dual-chain iterations (pairs 0..23), then single-chain tail (pair 24).
    for (int q = 0; q < 12; q++) {
        int jA = 2 * q, jB = 2 * q + 1;
        Chain A = seed_pair(sh_d2[warp][jA], sh_p2[warp][jA],
                            sh_a2[warp][jA], sh_an2[warp][jA], wpos2);
        Chain B = seed_pair(sh_d2[warp][jB], sh_p2[warp][jB],
                            sh_a2[warp][jB], sh_an2[warp][jB], wpos2);

        #pragma unroll
        for (int k = 0; k < KSTEPS; k++) {
            acc[k] = add2(acc[k], A.p_cur);
            acc[k] = add2(acc[k], B.p_cur);
            ull rA = ((k + 1) & 1) ? A.rp : A.rn;
            ull rB = ((k + 1) & 1) ? B.rp : B.rn;
            ull nA = fma2(rA, A.p_cur, A.p_prev);
            ull nB = fma2(rB, B.p_cur, B.p_prev);
            A.p_prev = A.p_cur; A.p_cur = nA;
            B.p_prev = B.p_cur; B.p_cur = nB;
        }
    }
    {
        Chain A = seed_pair(sh_d2[warp][24], sh_p2[warp][24],
                            sh_a2[warp][24], sh_an2[warp][24], wpos2);
        #pragma unroll
        for (int k = 0; k < KSTEPS; k++) {
            acc[k] = add2(acc[k], A.p_cur);
            ull nA = fma2(((k + 1) & 1) ? A.rp : A.rn, A.p_cur, A.p_prev);
            A.p_prev = A.p_cur; A.p_cur = nA;
        }
    }

    // Hann window + overlap-add. This warp covers output
    // [(t-1)*512 + wh*512 + ...], 16 strided samples per lane.
    float* outb = out + b * (TT * HOPS);
    const int pbase = (t - 1) * HOPS + wh * HOPS + lane;
    const int wbase = wh * HOPS + lane;
    #pragma unroll
    for (int k = 0; k < KSTEPS; k++) {
        float lo, hi;
        unpack2(acc[k], lo, hi);
        float s = lo + hi;
        float hann = sh_hann[wbase + 32 * k];
        float v = (((k >> 1) & 1) == 0) ? (s * hann) : (s * (-hann));
        int p = pbase + 32 * k;
        if (p >= 0 && p < TT * HOPS) {
            atomicAdd(outb + p, v);
        }
    }
}

extern "C" void kernel_launch(void* const* d_in, const int* in_sizes, int n_in,
                              void* d_out, int out_size) {
    const float* ampl  = (const float*)d_in[0];
    const float* phase = (const float*)d_in[1];
    const float* f0    = (const float*)d_in[2];
    float* out = (float*)d_out;

    cudaMemsetAsync(out, 0, (size_t)out_size * sizeof(float));
    sinstack_kernel<<<1600, 128>>>(ampl, phase, f0, out);
}

// round 6
// speedup vs baseline: 1.4451x; 1.1001x over previous
#include <cuda_runtime.h>

#define HOPS 512
#define NHARM 100
#define TT 400
#define NHALF 50
#define NPAIR 25
#define KSTEPS 16   // window samples per lane (half window per warp)

typedef unsigned long long ull;

// ---- packed f32x2 helpers (sm_103a) ----
__device__ __forceinline__ ull pack2(float lo, float hi) {
    ull r; asm("mov.b64 %0, {%1, %2};" : "=l"(r) : "f"(lo), "f"(hi)); return r;
}
__device__ __forceinline__ void unpack2(ull v, float& lo, float& hi) {
    asm("mov.b64 {%0, %1}, %2;" : "=f"(lo), "=f"(hi) : "l"(v));
}
__device__ __forceinline__ ull fma2(ull a, ull b, ull c) {
    ull d; asm("fma.rn.f32x2 %0, %1, %2, %3;" : "=l"(d) : "l"(a), "l"(b), "l"(c)); return d;
}
__device__ __forceinline__ ull add2(ull a, ull b) {
    ull d; asm("add.rn.f32x2 %0, %1, %2;" : "=l"(d) : "l"(a), "l"(b)); return d;
}
__device__ __forceinline__ ull mul2(ull a, ull b) {
    ull d; asm("mul.rn.f32x2 %0, %1, %2;" : "=l"(d) : "l"(a), "l"(b)); return d;
}

struct Chain { ull p_prev, p_cur, rp, rn; };

// Cheap seeds: raw MUFU (|theta| <= ~87 rad here; HW internal reduction
// error ~2e-5 rad, far inside the 1e-3 budget). 7 packed fma-class ops,
// 6 MUFU per harmonic pair.
__device__ __forceinline__ Chain seed_pair(ull dd, ull pp, ull aa, ull aan, ull wpos2) {
    const ull K32N    = pack2(-32.0f, -32.0f);
    const ull NEGTWO2 = pack2(-2.0f, -2.0f);

    ull Dn2 = mul2(dd, K32N);                 // -D (cos is even)
    ull x2  = fma2(wpos2, dd, pp);            // theta
    ull xm2 = add2(x2, Dn2);                  // theta - D

    float xA, xB, mA, mB, DA, DB;
    unpack2(x2, xA, xB);
    unpack2(xm2, mA, mB);
    unpack2(Dn2, DA, DB);
    ull cth2  = pack2(__cosf(xA), __cosf(xB));
    ull cthm2 = pack2(__cosf(mA), __cosf(mB));
    ull cD2   = pack2(__cosf(DA), __cosf(DB));

    Chain c;
    c.p_cur  = mul2(aa, cth2);                // +a*cos(th)
    c.p_prev = mul2(aan, cthm2);              // -a*cos(th-D)
    c.rp = add2(cD2, cD2);                    // +2cos(D)
    c.rn = mul2(cD2, NEGTWO2);                // -2cos(D)
    return c;
}

// Block = one 512-sample output region r (of batch b): covers out[r*512,(r+1)*512).
// Contributors: frame t=r (window half wh=1) and frame t=r+1 (wh=0).
// 4 warps: (t, hh=0), (t, hh=1), (t+1, hh=0), (t+1, hh=1); each handles 50
// harmonics over the region's 512 samples (lane l owns s = l + 32k, k=0..15).
// Dual packed Chebyshev chains, seeds software-pipelined one pair ahead.
// Partials staged in shared; block sums and stores once — no atomics, no memset.
__global__ __launch_bounds__(128, 6) void sinstack_kernel(
    const float* __restrict__ ampl,
    const float* __restrict__ phase,
    const float* __restrict__ f0,
    float* __restrict__ out)
{
    __shared__ ull sh_d2[4][NPAIR];
    __shared__ ull sh_p2[4][NPAIR];
    __shared__ ull sh_a2[4][NPAIR];
    __shared__ ull sh_an2[4][NPAIR];
    __shared__ float sh_hann[1024];
    __shared__ float sh_part[4][512];

    const int warp = threadIdx.x >> 5;
    const int lane = threadIdx.x & 31;
    const int b = blockIdx.x / TT;
    const int r = blockIdx.x - b * TT;     // output region 0..399
    const int wh = 1 - (warp >> 1);        // warps 0,1: wh=1 (frame r); 2,3: wh=0 (frame r+1)
    const int hh = warp & 1;               // harmonic half
    const int t  = r + (warp >> 1);        // frame index (may be TT: dead warp)
    const bool alive = (t < TT);

    {
        const float HSTEP = 6.283185307179586f / 1024.0f;
        #pragma unroll
        for (int i = 0; i < 8; i++) {
            int w = threadIdx.x + 128 * i;
            sh_hann[w] = fmaf(-0.5f, __cosf((float)w * HSTEP), 0.5f);
        }
    }

    if (alive) {
        const float K2PI_SR = 6.283185307179586f / 44100.0f;
        const int base = b * NHARM * TT + (hh * NHALF) * TT + t;
        float* fd = (float*)&sh_d2[warp][0];
        float* fp = (float*)&sh_p2[warp][0];
        float* fa = (float*)&sh_a2[warp][0];
        float* fn = (float*)&sh_an2[warp][0];
        for (int j = lane; j < NHALF; j += 32) {
            int idx = base + j * TT;
            float a = ampl[idx];
            fd[j] = f0[idx] * K2PI_SR;
            fp[j] = phase[idx];
            fa[j] = a;
            fn[j] = -a;
        }
    }
    __syncwarp();

    ull acc[KSTEPS];
    #pragma unroll
    for (int k = 0; k < KSTEPS; k++) acc[k] = 0ull;

    if (alive) {
        // window position of lane's k=0 sample: wh=1 -> lane; wh=0 -> lane-512
        const float wpos = (float)(lane + (wh ? 0 : -HOPS));
        const ull wpos2 = pack2(wpos, wpos);

        Chain A = seed_pair(sh_d2[warp][0], sh_p2[warp][0],
                            sh_a2[warp][0], sh_an2[warp][0], wpos2);
        Chain B = seed_pair(sh_d2[warp][1], sh_p2[warp][1],
                            sh_a2[warp][1], sh_an2[warp][1], wpos2);

        #pragma unroll 1
        for (int q = 0; q < 11; q++) {
            int j = 2 * q + 2;
            Chain An = seed_pair(sh_d2[warp][j], sh_p2[warp][j],
                                 sh_a2[warp][j], sh_an2[warp][j], wpos2);
            Chain Bn = seed_pair(sh_d2[warp][j+1], sh_p2[warp][j+1],
                                 sh_a2[warp][j+1], sh_an2[warp][j+1], wpos2);
            #pragma unroll
            for (int k = 0; k < KSTEPS; k++) {
                acc[k] = add2(acc[k], A.p_cur);
                acc[k] = add2(acc[k], B.p_cur);
                ull nA = fma2(((k + 1) & 1) ? A.rp : A.rn, A.p_cur, A.p_prev);
                ull nB = fma2(((k + 1) & 1) ? B.rp : B.rn, B.p_cur, B.p_prev);
                A.p_prev = A.p_cur; A.p_cur = nA;
                B.p_prev = B.p_cur; B.p_cur = nB;
            }
            A = An; B = Bn;
        }
        {
            // last dual pair (22,23 loaded as A,B) + single tail pair 24
            Chain C = seed_pair(sh_d2[warp][24], sh_p2[warp][24],
                                sh_a2[warp][24], sh_an2[warp][24], wpos2);
            #pragma unroll
            for (int k = 0; k < KSTEPS; k++) {
                acc[k] = add2(acc[k], A.p_cur);
                acc[k] = add2(acc[k], B.p_cur);
                ull nA = fma2(((k + 1) & 1) ? A.rp : A.rn, A.p_cur, A.p_prev);
                ull nB = fma2(((k + 1) & 1) ? B.rp : B.rn, B.p_cur, B.p_prev);
                A.p_prev = A.p_cur; A.p_cur = nA;
                B.p_prev = B.p_cur; B.p_cur = nB;
            }
            #pragma unroll
            for (int k = 0; k < KSTEPS; k++) {
                acc[k] = add2(acc[k], C.p_cur);
                ull nC = fma2(((k + 1) & 1) ? C.rp : C.rn, C.p_cur, C.p_prev);
                C.p_prev = C.p_cur; C.p_cur = nC;
            }
        }
    }

    // Stage windowed partials: sample s = lane + 32k of the region.
    {
        const int hbase = wh * HOPS + lane;     // window offset of s
        #pragma unroll
        for (int k = 0; k < KSTEPS; k++) {
            float lo, hi;
            unpack2(acc[k], lo, hi);
            float s = lo + hi;
            float hann = sh_hann[hbase + 32 * k];
            // sigma_k = + for k%4 in {0,1}, - for {2,3}
            float v = (((k >> 1) & 1) == 0) ? (s * hann) : (s * (-hann));
            sh_part[warp][lane + 32 * k] = alive ? v : 0.0f;
        }
    }
    __syncthreads();

    // Combine 4 partials, single coalesced store.
    {
        float* outp = out + b * (TT * HOPS) + r * HOPS;
        #pragma unroll
        for (int i = threadIdx.x; i < HOPS; i += 128) {
            float v = (sh_part[0][i] + sh_part[1][i]) + (sh_part[2][i] + sh_part[3][i]);
            outp[i] = v;
        }
    }
}

extern "C" void kernel_launch(void* const* d_in, const int* in_sizes, int n_in,
                              void* d_out, int out_size) {
    const float* ampl  = (const float*)d_in[0];
    const float* phase = (const float*)d_in[1];
    const float* f0    = (const float*)d_in[2];
    float* out = (float*)d_out;

    sinstack_kernel<<<1600, 128>>>(ampl, phase, f0, out);
}

// round 7
// speedup vs baseline: 1.4696x; 1.0170x over previous
#include <cuda_runtime.h>

#define HOPS 512
#define NHARM 100
#define TT 400
#define NHALF 50
#define NPAIR 25
#define KSTEPS 16   // window samples per lane (half window per warp)

typedef unsigned long long ull;

#define SIGN64 0x8000000080000000ull

// ---- packed f32x2 helpers (sm_103a) ----
__device__ __forceinline__ ull pack2(float lo, float hi) {
    ull r; asm("mov.b64 %0, {%1, %2};" : "=l"(r) : "f"(lo), "f"(hi)); return r;
}
__device__ __forceinline__ void unpack2(ull v, float& lo, float& hi) {
    asm("mov.b64 {%0, %1}, %2;" : "=f"(lo), "=f"(hi) : "l"(v));
}
__device__ __forceinline__ ull fma2(ull a, ull b, ull c) {
    ull d; asm("fma.rn.f32x2 %0, %1, %2, %3;" : "=l"(d) : "l"(a), "l"(b), "l"(c)); return d;
}
__device__ __forceinline__ ull add2(ull a, ull b) {
    ull d; asm("add.rn.f32x2 %0, %1, %2;" : "=l"(d) : "l"(a), "l"(b)); return d;
}
__device__ __forceinline__ ull mul2(ull a, ull b) {
    ull d; asm("mul.rn.f32x2 %0, %1, %2;" : "=l"(d) : "l"(a), "l"(b)); return d;
}

struct Chain { ull p_prev, p_cur, rp, rn; };

// Lean seeds: theta and theta-D via two fma2 against different wpos
// constants; r = 2cos(32*delta) comes precomputed from shared; negations
// are 64-bit XORs (alu pipe). 4 fma-class + 4 MUFU per harmonic pair.
__device__ __forceinline__ Chain seed_pair(ull dd, ull pp, ull aa, ull rp,
                                           ull wpos2, ull wm2) {
    ull x2  = fma2(wpos2, dd, pp);            // theta
    ull xm2 = fma2(wm2,   dd, pp);            // theta - D
    float xA, xB, mA, mB;
    unpack2(x2, xA, xB);
    unpack2(xm2, mA, mB);
    ull cth2  = pack2(__cosf(xA), __cosf(xB));
    ull cthm2 = pack2(__cosf(mA), __cosf(mB));

    Chain c;
    c.p_cur  = mul2(aa, cth2);                // +a*cos(th)
    c.p_prev = mul2(aa ^ SIGN64, cthm2);      // -a*cos(th-D)
    c.rp = rp;                                // +2cos(D) (precomputed)
    c.rn = rp ^ SIGN64;                       // -2cos(D)  (alu)
    return c;
}

// Block = one 512-sample output region r of batch b. Contributors: frame t=r
// (window half 1) and frame t=r+1 (window half 0). 4 warps = 2 frames x 2
// harmonic halves; lane l owns region samples s = l + 32k, k=0..15.
// Dual packed Chebyshev chains (sigma trick ++-- keeps them subtraction-free),
// seeds software-pipelined one pair ahead. Partials staged in shared; one
// coalesced store per region — no atomics, no global zeroing pass.
__global__ __launch_bounds__(128, 6) void sinstack_kernel(
    const float* __restrict__ ampl,
    const float* __restrict__ phase,
    const float* __restrict__ f0,
    float* __restrict__ out)
{
    __shared__ ull sh_d2[4][NPAIR];
    __shared__ ull sh_p2[4][NPAIR];
    __shared__ ull sh_a2[4][NPAIR];
    __shared__ ull sh_r2[4][NPAIR];     // 2*cos(32*delta), precomputed
    __shared__ float sh_hann[1024];
    __shared__ float sh_part[4][512];

    const int warp = threadIdx.x >> 5;
    const int lane = threadIdx.x & 31;
    const int b = blockIdx.x / TT;
    const int r = blockIdx.x - b * TT;     // output region 0..399
    const int wh = 1 - (warp >> 1);        // warps 0,1: frame r (wh=1); 2,3: frame r+1 (wh=0)
    const int hh = warp & 1;               // harmonic half
    const int t  = r + (warp >> 1);        // frame index (may be TT: dead warp)
    const bool alive = (t < TT);

    {
        const float HSTEP = 6.283185307179586f / 1024.0f;
        #pragma unroll
        for (int i = 0; i < 8; i++) {
            int w = threadIdx.x + 128 * i;
            sh_hann[w] = fmaf(-0.5f, __cosf((float)w * HSTEP), 0.5f);
        }
    }

    if (alive) {
        const float K2PI_SR = 6.283185307179586f / 44100.0f;
        const int base = b * NHARM * TT + (hh * NHALF) * TT + t;
        float* fd = (float*)&sh_d2[warp][0];
        float* fp = (float*)&sh_p2[warp][0];
        float* fa = (float*)&sh_a2[warp][0];
        float* fr = (float*)&sh_r2[warp][0];
        for (int j = lane; j < NHALF; j += 32) {
            int idx = base + j * TT;
            float d = f0[idx] * K2PI_SR;
            fd[j] = d;
            fp[j] = phase[idx];
            fa[j] = ampl[idx];
            fr[j] = 2.0f * __cosf(32.0f * d);   // one-time MUFU, off hot path
        }
    }
    __syncwarp();

    ull acc[KSTEPS];
    #pragma unroll
    for (int k = 0; k < KSTEPS; k++) acc[k] = 0ull;

    if (alive) {
        // window position of lane's k=0 sample: wh=1 -> lane; wh=0 -> lane-512
        const float wpos = (float)(lane + (wh ? 0 : -HOPS));
        const ull wpos2 = pack2(wpos, wpos);
        const ull wm2   = pack2(wpos - 32.0f, wpos - 32.0f);

        Chain A = seed_pair(sh_d2[warp][0], sh_p2[warp][0], sh_a2[warp][0],
                            sh_r2[warp][0], wpos2, wm2);
        Chain B = seed_pair(sh_d2[warp][1], sh_p2[warp][1], sh_a2[warp][1],
                            sh_r2[warp][1], wpos2, wm2);

        #pragma unroll 1
        for (int q = 0; q < 11; q++) {
            int j = 2 * q + 2;
            Chain An = seed_pair(sh_d2[warp][j], sh_p2[warp][j], sh_a2[warp][j],
                                 sh_r2[warp][j], wpos2, wm2);
            Chain Bn = seed_pair(sh_d2[warp][j+1], sh_p2[warp][j+1], sh_a2[warp][j+1],
                                 sh_r2[warp][j+1], wpos2, wm2);
            #pragma unroll
            for (int k = 0; k < KSTEPS; k++) {
                acc[k] = add2(acc[k], A.p_cur);
                acc[k] = add2(acc[k], B.p_cur);
                ull nA = fma2(((k + 1) & 1) ? A.rp : A.rn, A.p_cur, A.p_prev);
                ull nB = fma2(((k + 1) & 1) ? B.rp : B.rn, B.p_cur, B.p_prev);
                A.p_prev = A.p_cur; A.p_cur = nA;
                B.p_prev = B.p_cur; B.p_cur = nB;
            }
            A = An; B = Bn;
        }
        {
            // last dual pair (22,23) + single tail pair 24
            Chain C = seed_pair(sh_d2[warp][24], sh_p2[warp][24], sh_a2[warp][24],
                                sh_r2[warp][24], wpos2, wm2);
            #pragma unroll
            for (int k = 0; k < KSTEPS; k++) {
                acc[k] = add2(acc[k], A.p_cur);
                acc[k] = add2(acc[k], B.p_cur);
                ull nA = fma2(((k + 1) & 1) ? A.rp : A.rn, A.p_cur, A.p_prev);
                ull nB = fma2(((k + 1) & 1) ? B.rp : B.rn, B.p_cur, B.p_prev);
                A.p_prev = A.p_cur; A.p_cur = nA;
                B.p_prev = B.p_cur; B.p_cur = nB;
            }
            #pragma unroll
            for (int k = 0; k < KSTEPS; k++) {
                acc[k] = add2(acc[k], C.p_cur);
                ull nC = fma2(((k + 1) & 1) ? C.rp : C.rn, C.p_cur, C.p_prev);
                C.p_prev = C.p_cur; C.p_cur = nC;
            }
        }
    }

    // Stage windowed partials: sample s = lane + 32k of the region.
    {
        const int hbase = wh * HOPS + lane;
        #pragma unroll
        for (int k = 0; k < KSTEPS; k++) {
            float lo, hi;
            unpack2(acc[k], lo, hi);
            float s = lo + hi;
            float hann = sh_hann[hbase + 32 * k];
            // sigma_k = + for k%4 in {0,1}, - for {2,3}
            float v = (((k >> 1) & 1) == 0) ? (s * hann) : (s * (-hann));
            sh_part[warp][lane + 32 * k] = alive ? v : 0.0f;
        }
    }
    __syncthreads();

    // Combine 4 partials, single coalesced store.
    {
        float* outp = out + b * (TT * HOPS) + r * HOPS;
        #pragma unroll
        for (int i = threadIdx.x; i < HOPS; i += 128) {
            float v = (sh_part[0][i] + sh_part[1][i]) + (sh_part[2][i] + sh_part[3][i]);
            outp[i] = v;
        }
    }
}

extern "C" void kernel_launch(void* const* d_in, const int* in_sizes, int n_in,
                              void* d_out, int out_size) {
    const float* ampl  = (const float*)d_in[0];
    const float* phase = (const float*)d_in[1];
    const float* f0    = (const float*)d_in[2];
    float* out = (float*)d_out;

    sinstack_kernel<<<1600, 128>>>(ampl, phase, f0, out);
}